// round 13
// baseline (speedup 1.0000x reference)
#include <cuda_runtime.h>

#define Bn 4
#define Nn 512
#define Dn 128
#define Hn 4
#define Cn 32

typedef unsigned long long ull;

// Scratch (allocation-free: __device__ globals)
__device__ float g_XL[Bn * Nn * Dn];
__device__ float g_XR[Bn * Nn * Dn];
__device__ float g_U[Bn * Nn * Hn];   // 0.6 * att . xr   per (b,n,h)
__device__ float g_V[Bn * Nn * Hn];   // 0.6 * att . xl   per (b,n,h)

// ---- packed f32x2 helpers (Blackwell FFMA2 path) ----
__device__ __forceinline__ ull pk(float a, float b) {
    ull r;
    asm("mov.b64 %0, {%1,%2};" : "=l"(r) : "r"(__float_as_uint(a)), "r"(__float_as_uint(b)));
    return r;
}
__device__ __forceinline__ void upk(ull v, float& a, float& b) {
    unsigned x, y;
    asm("mov.b64 {%0,%1}, %2;" : "=r"(x), "=r"(y) : "l"(v));
    a = __uint_as_float(x); b = __uint_as_float(y);
}
__device__ __forceinline__ ull addx2(ull a, ull b) {
    ull r; asm("add.rn.f32x2 %0, %1, %2;" : "=l"(r) : "l"(a), "l"(b)); return r;
}
__device__ __forceinline__ ull mulx2(ull a, ull b) {
    ull r; asm("mul.rn.f32x2 %0, %1, %2;" : "=l"(r) : "l"(a), "l"(b)); return r;
}
__device__ __forceinline__ ull fmax2(ull a, ull b, ull c) {
    ull r; asm("fma.rn.f32x2 %0, %1, %2, %3;" : "=l"(r) : "l"(a), "l"(b), "l"(c)); return r;
}

// =====================================================================
// Kernel 1: XL = xWl + bl, XR = xWr + br, plus U = 0.6*att.XR, V = 0.6*att.XL
// Grid (32, 4), 512 threads. CTA handles 16 rows of one batch, both matrices.
// =====================================================================
__global__ void __launch_bounds__(512) gat_pre(
    const float* __restrict__ x,
    const float* __restrict__ Wl, const float* __restrict__ bl,
    const float* __restrict__ Wr, const float* __restrict__ br,
    const float* __restrict__ att)
{
    __shared__ __align__(16) float xs[16][128];
    const int b  = blockIdx.y;
    const int r0 = blockIdx.x * 16;
    const int t  = threadIdx.x;

    // cooperative load of 16 x-rows (2048 floats = 512 float4)
    ((float4*)xs)[t] = ((const float4*)(x + (size_t)(b * Nn + r0) * Dn))[t];
    __syncthreads();

    const int col = t & 127;
    const int q   = t >> 7;        // 0..3
    const int mat = q & 1;         // 0 -> Wl/XL/V, 1 -> Wr/XR/U
    const int rh  = q >> 1;        // row half (8 rows each)

    const float* W  = mat ? Wr : Wl;
    const float  bc = (mat ? br : bl)[col];

    float acc[8];
#pragma unroll
    for (int r = 0; r < 8; r++) acc[r] = 0.f;

    for (int k = 0; k < 128; k += 4) {
        const float w0 = W[(k + 0) * 128 + col];
        const float w1 = W[(k + 1) * 128 + col];
        const float w2 = W[(k + 2) * 128 + col];
        const float w3 = W[(k + 3) * 128 + col];
#pragma unroll
        for (int r = 0; r < 8; r++) {
            const float4 xv = *(const float4*)&xs[rh * 8 + r][k];
            acc[r] = fmaf(xv.x, w0, acc[r]);
            acc[r] = fmaf(xv.y, w1, acc[r]);
            acc[r] = fmaf(xv.z, w2, acc[r]);
            acc[r] = fmaf(xv.w, w3, acc[r]);
        }
    }

    float* Xo  = mat ? g_XR : g_XL;
    float* UVo = mat ? g_U  : g_V;
    const int   head = col >> 5;
    const float aw   = att[col];   // att[head*32 + c] == att[col]

#pragma unroll
    for (int r = 0; r < 8; r++) {
        const int row = r0 + rh * 8 + r;
        const float val = acc[r] + bc;
        Xo[(size_t)(b * Nn + row) * Dn + col] = val;
        float s = aw * val;
#pragma unroll
        for (int off = 16; off; off >>= 1)
            s += __shfl_xor_sync(0xffffffffu, s, off);
        if ((t & 31) == 0)
            UVo[(size_t)(b * Nn + row) * Hn + head] = 0.6f * s;
    }
}

// =====================================================================
// Kernel 2: fused score + masked online-softmax + weighted sum.
// Grid (32, 4), 256 threads. CTA = 16 target rows i, all heads.
// thread t: i_local = t&15, h = (t>>4)&3, rep = t>>6 (j stride 4).
// =====================================================================
__global__ void __launch_bounds__(256) gat_main(
    const int*   __restrict__ adj,
    const float* __restrict__ att,
    const float* __restrict__ bias,
    float*       __restrict__ out)
{
    const float L2E  = 1.4426950408889634f;
    const ull   ABS2 = 0x7FFFFFFF7FFFFFFFULL;

    const int b   = blockIdx.y;
    const int i0  = blockIdx.x * 16;
    const int t   = threadIdx.x;
    const int il  = t & 15;
    const int h   = (t >> 4) & 3;
    const int rep = t >> 6;
    const int i   = i0 + il;

    // persistent packed registers
    ull att2[16], xr2[16], acc2[16];
    {
        const float* ap  = att + h * 32;
        const float* xrp = g_XR + (size_t)(b * Nn + i) * Dn + h * 32;
#pragma unroll
        for (int k = 0; k < 16; k++) {
            att2[k] = pk(0.4f * ap[2 * k], 0.4f * ap[2 * k + 1]);
            xr2[k]  = pk(xrp[2 * k], xrp[2 * k + 1]);
            acc2[k] = 0ULL;
        }
    }
    const float u = g_U[(size_t)(b * Nn + i) * Hn + h];

    const float* xlb  = g_XL + (size_t)b * Nn * Dn;
    const float* vb   = g_V + (size_t)b * Nn * Hn;
    const int*   adjb = adj + (size_t)b * Nn * Nn;

    float m = -3.0e29f;   // sentinel init: masked e = -1e30 stays below it
    float l = 0.f;

    for (int j = rep; j < Nn; j += 4) {
        const int   av = adjb[j * Nn + i];            // edge j -> i
        const float v  = vb[j * Hn + h];

        const float4* xp = (const float4*)(xlb + j * Dn + h * 32);
        ull xl2[16];
#pragma unroll
        for (int k = 0; k < 8; k++) {
            const float4 q4 = xp[k];
            xl2[2 * k]     = pk(q4.x, q4.y);
            xl2[2 * k + 1] = pk(q4.z, q4.w);
        }

        // w = sum_c 0.4*att_c * |xr_c + xl_c|   (4-way packed accumulators)
        ull w0 = 0ULL, w1 = 0ULL, w2a = 0ULL, w3 = 0ULL;
#pragma unroll
        for (int k = 0; k < 16; k += 4) {
            const ull s0 = addx2(xr2[k],     xl2[k])     & ABS2;
            const ull s1 = addx2(xr2[k + 1], xl2[k + 1]) & ABS2;
            const ull s2 = addx2(xr2[k + 2], xl2[k + 2]) & ABS2;
            const ull s3 = addx2(xr2[k + 3], xl2[k + 3]) & ABS2;
            w0  = fmax2(att2[k],     s0, w0);
            w1  = fmax2(att2[k + 1], s1, w1);
            w2a = fmax2(att2[k + 2], s2, w2a);
            w3  = fmax2(att2[k + 3], s3, w3);
        }
        const ull ws = addx2(addx2(w0, w1), addx2(w2a, w3));
        float wa, wb; upk(ws, wa, wb);

        const bool valid = (av != 0) || (j == i);
        const float e = valid ? (u + v + wa + wb) : -1.0e30f;

        float p;
        if (e > m) {
            const float corr = exp2f((m - e) * L2E);
            const ull c2 = pk(corr, corr);
#pragma unroll
            for (int k = 0; k < 16; k++) acc2[k] = mulx2(acc2[k], c2);
            l *= corr;
            m  = e;
            p  = 1.f;
        } else {
            p = exp2f((e - m) * L2E);   // masked: exp2(-huge) = 0
        }
        l += p;
        const ull p2 = pk(p, p);
#pragma unroll
        for (int k = 0; k < 16; k++) acc2[k] = fmax2(p2, xl2[k], acc2[k]);
    }

    // ---- combine the 4 rep-partials per (i,h) ----
    __shared__ float sm_m[4][64], sm_l[4][64], sm_L[64];
    __shared__ float sm_acc[64][33];   // padded: conflict-free

    const int ih = t & 63;   // il + 16*h
    sm_m[rep][ih] = m;
    sm_l[rep][ih] = l;
    __syncthreads();

    const float M = fmaxf(fmaxf(sm_m[0][ih], sm_m[1][ih]),
                          fmaxf(sm_m[2][ih], sm_m[3][ih]));
    float L = 0.f;
#pragma unroll
    for (int r = 0; r < 4; r++)
        L += sm_l[r][ih] * exp2f((sm_m[r][ih] - M) * L2E);
    if (rep == 0) sm_L[ih] = L;

    const float sc = exp2f((m - M) * L2E);
    float av_[32];
#pragma unroll
    for (int k = 0; k < 16; k++) upk(acc2[k], av_[2 * k], av_[2 * k + 1]);

#pragma unroll
    for (int r = 0; r < 4; r++) {
        if (rep == r) {
            if (r == 0) {
#pragma unroll
                for (int c = 0; c < 32; c++) sm_acc[ih][c] = av_[c] * sc;
            } else {
#pragma unroll
                for (int c = 0; c < 32; c++) sm_acc[ih][c] += av_[c] * sc;
            }
        }
        __syncthreads();
    }

    // ---- normalize + bias, coalesced write ----
    float* ob = out + (size_t)(b * Nn + i0) * Dn;
    for (int idx = t; idx < 16 * Dn; idx += 256) {
        const int ir = idx >> 7;
        const int c  = idx & 127;
        const int k2 = ir + 16 * (c >> 5);
        ob[idx] = sm_acc[k2][c & 31] / sm_L[k2] + bias[c];
    }
}

extern "C" void kernel_launch(void* const* d_in, const int* in_sizes, int n_in,
                              void* d_out, int out_size) {
    const float* x    = (const float*)d_in[0];
    const int*   adj  = (const int*)  d_in[1];
    const float* Wl   = (const float*)d_in[2];
    const float* bl   = (const float*)d_in[3];
    const float* Wr   = (const float*)d_in[4];
    const float* br   = (const float*)d_in[5];
    const float* att  = (const float*)d_in[6];
    const float* bias = (const float*)d_in[7];
    float* out = (float*)d_out;

    gat_pre <<<dim3(Nn / 16, Bn), 512>>>(x, Wl, bl, Wr, br, att);
    gat_main<<<dim3(Nn / 16, Bn), 256>>>(adj, att, bias, out);
}

// round 14
// speedup vs baseline: 1.0098x; 1.0098x over previous
#include <cuda_runtime.h>

#define Bn 4
#define Nn 512
#define Dn 128
#define Hn 4
#define Cn 32

typedef unsigned long long ull;

// Scratch (allocation-free: __device__ globals)
__device__ float g_XL[Bn * Nn * Dn];
__device__ float g_XR[Bn * Nn * Dn];
__device__ float g_U[Bn * Nn * Hn];   // 0.6 * att . xr   per (b,n,h)
__device__ float g_V[Bn * Nn * Hn];   // 0.6 * att . xl   per (b,n,h)

// ---- packed f32x2 helpers (Blackwell FFMA2 path) ----
__device__ __forceinline__ ull pk(float a, float b) {
    ull r;
    asm("mov.b64 %0, {%1,%2};" : "=l"(r) : "r"(__float_as_uint(a)), "r"(__float_as_uint(b)));
    return r;
}
__device__ __forceinline__ void upk(ull v, float& a, float& b) {
    unsigned x, y;
    asm("mov.b64 {%0,%1}, %2;" : "=r"(x), "=r"(y) : "l"(v));
    a = __uint_as_float(x); b = __uint_as_float(y);
}
__device__ __forceinline__ ull addx2(ull a, ull b) {
    ull r; asm("add.rn.f32x2 %0, %1, %2;" : "=l"(r) : "l"(a), "l"(b)); return r;
}
__device__ __forceinline__ ull mulx2(ull a, ull b) {
    ull r; asm("mul.rn.f32x2 %0, %1, %2;" : "=l"(r) : "l"(a), "l"(b)); return r;
}
__device__ __forceinline__ ull fmax2(ull a, ull b, ull c) {
    ull r; asm("fma.rn.f32x2 %0, %1, %2, %3;" : "=l"(r) : "l"(a), "l"(b), "l"(c)); return r;
}

// =====================================================================
// Kernel 1: XL = xWl + bl, XR = xWr + br, plus U = 0.6*att.XR, V = 0.6*att.XL
// Grid (32, 4), 512 threads. CTA handles 16 rows of one batch, both matrices.
// =====================================================================
__global__ void __launch_bounds__(512) gat_pre(
    const float* __restrict__ x,
    const float* __restrict__ Wl, const float* __restrict__ bl,
    const float* __restrict__ Wr, const float* __restrict__ br,
    const float* __restrict__ att)
{
    __shared__ __align__(16) float xs[16][128];
    const int b  = blockIdx.y;
    const int r0 = blockIdx.x * 16;
    const int t  = threadIdx.x;

    // cooperative load of 16 x-rows (2048 floats = 512 float4)
    ((float4*)xs)[t] = ((const float4*)(x + (size_t)(b * Nn + r0) * Dn))[t];
    __syncthreads();

    const int col = t & 127;
    const int q   = t >> 7;        // 0..3
    const int mat = q & 1;         // 0 -> Wl/XL/V, 1 -> Wr/XR/U
    const int rh  = q >> 1;        // row half (8 rows each)

    const float* W  = mat ? Wr : Wl;
    const float  bc = (mat ? br : bl)[col];

    float acc[8];
#pragma unroll
    for (int r = 0; r < 8; r++) acc[r] = 0.f;

    for (int k = 0; k < 128; k += 4) {
        const float w0 = W[(k + 0) * 128 + col];
        const float w1 = W[(k + 1) * 128 + col];
        const float w2 = W[(k + 2) * 128 + col];
        const float w3 = W[(k + 3) * 128 + col];
#pragma unroll
        for (int r = 0; r < 8; r++) {
            const float4 xv = *(const float4*)&xs[rh * 8 + r][k];
            acc[r] = fmaf(xv.x, w0, acc[r]);
            acc[r] = fmaf(xv.y, w1, acc[r]);
            acc[r] = fmaf(xv.z, w2, acc[r]);
            acc[r] = fmaf(xv.w, w3, acc[r]);
        }
    }

    float* Xo  = mat ? g_XR : g_XL;
    float* UVo = mat ? g_U  : g_V;
    const int   head = col >> 5;
    const float aw   = att[col];   // att[head*32 + c] == att[col]

#pragma unroll
    for (int r = 0; r < 8; r++) {
        const int row = r0 + rh * 8 + r;
        const float val = acc[r] + bc;
        Xo[(size_t)(b * Nn + row) * Dn + col] = val;
        float s = aw * val;
#pragma unroll
        for (int off = 16; off; off >>= 1)
            s += __shfl_xor_sync(0xffffffffu, s, off);
        if ((t & 31) == 0)
            UVo[(size_t)(b * Nn + row) * Hn + head] = 0.6f * s;
    }
}

// =====================================================================
// Kernel 2: fused score + masked online-softmax + weighted sum.
// Grid (32, 4), 256 threads. CTA = 16 target rows i, all heads.
// thread t: i_local = t&15, h = (t>>4)&3, rep = t>>6 (j stride 4).
// =====================================================================
__global__ void __launch_bounds__(256) gat_main(
    const int*   __restrict__ adj,
    const float* __restrict__ att,
    const float* __restrict__ bias,
    float*       __restrict__ out)
{
    const float L2E  = 1.4426950408889634f;
    const ull   ABS2 = 0x7FFFFFFF7FFFFFFFULL;

    const int b   = blockIdx.y;
    const int i0  = blockIdx.x * 16;
    const int t   = threadIdx.x;
    const int il  = t & 15;
    const int h   = (t >> 4) & 3;
    const int rep = t >> 6;
    const int i   = i0 + il;

    // persistent packed registers
    ull att2[16], xr2[16], acc2[16];
    {
        const float* ap  = att + h * 32;
        const float* xrp = g_XR + (size_t)(b * Nn + i) * Dn + h * 32;
#pragma unroll
        for (int k = 0; k < 16; k++) {
            att2[k] = pk(0.4f * ap[2 * k], 0.4f * ap[2 * k + 1]);
            xr2[k]  = pk(xrp[2 * k], xrp[2 * k + 1]);
            acc2[k] = 0ULL;
        }
    }
    const float u = g_U[(size_t)(b * Nn + i) * Hn + h];

    const float* xlb  = g_XL + (size_t)b * Nn * Dn;
    const float* vb   = g_V + (size_t)b * Nn * Hn;
    const int*   adjb = adj + (size_t)b * Nn * Nn;

    float m = -3.0e29f;   // sentinel init: masked e = -1e30 stays below it
    float l = 0.f;

    for (int j = rep; j < Nn; j += 4) {
        const int   av = adjb[j * Nn + i];            // edge j -> i
        const float v  = vb[j * Hn + h];

        const float4* xp = (const float4*)(xlb + j * Dn + h * 32);
        ull xl2[16];
#pragma unroll
        for (int k = 0; k < 8; k++) {
            const float4 q4 = xp[k];
            xl2[2 * k]     = pk(q4.x, q4.y);
            xl2[2 * k + 1] = pk(q4.z, q4.w);
        }

        // w = sum_c 0.4*att_c * |xr_c + xl_c|   (4-way packed accumulators)
        ull w0 = 0ULL, w1 = 0ULL, w2a = 0ULL, w3 = 0ULL;
#pragma unroll
        for (int k = 0; k < 16; k += 4) {
            const ull s0 = addx2(xr2[k],     xl2[k])     & ABS2;
            const ull s1 = addx2(xr2[k + 1], xl2[k + 1]) & ABS2;
            const ull s2 = addx2(xr2[k + 2], xl2[k + 2]) & ABS2;
            const ull s3 = addx2(xr2[k + 3], xl2[k + 3]) & ABS2;
            w0  = fmax2(att2[k],     s0, w0);
            w1  = fmax2(att2[k + 1], s1, w1);
            w2a = fmax2(att2[k + 2], s2, w2a);
            w3  = fmax2(att2[k + 3], s3, w3);
        }
        const ull ws = addx2(addx2(w0, w1), addx2(w2a, w3));
        float wa, wb; upk(ws, wa, wb);

        const bool valid = (av != 0) || (j == i);
        const float e = valid ? (u + v + wa + wb) : -1.0e30f;

        float p;
        if (e > m) {
            const float corr = exp2f((m - e) * L2E);
            const ull c2 = pk(corr, corr);
#pragma unroll
            for (int k = 0; k < 16; k++) acc2[k] = mulx2(acc2[k], c2);
            l *= corr;
            m  = e;
            p  = 1.f;
        } else {
            p = exp2f((e - m) * L2E);   // masked: exp2(-huge) = 0
        }
        l += p;
        const ull p2 = pk(p, p);
#pragma unroll
        for (int k = 0; k < 16; k++) acc2[k] = fmax2(p2, xl2[k], acc2[k]);
    }

    // ---- combine the 4 rep-partials per (i,h) ----
    __shared__ float sm_m[4][64], sm_l[4][64], sm_L[64];
    __shared__ float sm_acc[64][33];   // padded: conflict-free

    const int ih = t & 63;   // il + 16*h
    sm_m[rep][ih] = m;
    sm_l[rep][ih] = l;
    __syncthreads();

    const float M = fmaxf(fmaxf(sm_m[0][ih], sm_m[1][ih]),
                          fmaxf(sm_m[2][ih], sm_m[3][ih]));
    float L = 0.f;
#pragma unroll
    for (int r = 0; r < 4; r++)
        L += sm_l[r][ih] * exp2f((sm_m[r][ih] - M) * L2E);
    if (rep == 0) sm_L[ih] = L;

    const float sc = exp2f((m - M) * L2E);
    float av_[32];
#pragma unroll
    for (int k = 0; k < 16; k++) upk(acc2[k], av_[2 * k], av_[2 * k + 1]);

#pragma unroll
    for (int r = 0; r < 4; r++) {
        if (rep == r) {
            if (r == 0) {
#pragma unroll
                for (int c = 0; c < 32; c++) sm_acc[ih][c] = av_[c] * sc;
            } else {
#pragma unroll
                for (int c = 0; c < 32; c++) sm_acc[ih][c] += av_[c] * sc;
            }
        }
        __syncthreads();
    }

    // ---- normalize + bias, coalesced write ----
    float* ob = out + (size_t)(b * Nn + i0) * Dn;
    for (int idx = t; idx < 16 * Dn; idx += 256) {
        const int ir = idx >> 7;
        const int c  = idx & 127;
        const int k2 = ir + 16 * (c >> 5);
        ob[idx] = sm_acc[k2][c & 31] / sm_L[k2] + bias[c];
    }
}

extern "C" void kernel_launch(void* const* d_in, const int* in_sizes, int n_in,
                              void* d_out, int out_size) {
    const float* x    = (const float*)d_in[0];
    const int*   adj  = (const int*)  d_in[1];
    const float* Wl   = (const float*)d_in[2];
    const float* bl   = (const float*)d_in[3];
    const float* Wr   = (const float*)d_in[4];
    const float* br   = (const float*)d_in[5];
    const float* att  = (const float*)d_in[6];
    const float* bias = (const float*)d_in[7];
    float* out = (float*)d_out;

    gat_pre <<<dim3(Nn / 16, Bn), 512>>>(x, Wl, bl, Wr, br, att);
    gat_main<<<dim3(Nn / 16, Bn), 256>>>(adj, att, bias, out);
}

// round 15
// speedup vs baseline: 1.0776x; 1.0671x over previous
#include <cuda_runtime.h>

#define Bn 4
#define Nn 512
#define Dn 128
#define Hn 4
#define Cn 32

typedef unsigned long long ull;

// Scratch (allocation-free: __device__ globals)
__device__ float g_XL[Bn * Nn * Dn];
__device__ float g_XR[Bn * Nn * Dn];
__device__ float g_U[Bn * Nn * Hn];   // 0.6 * att . xr   per (b,n,h)
__device__ float g_V[Bn * Nn * Hn];   // 0.6 * att . xl   per (b,n,h)

// ---- packed f32x2 helpers (Blackwell FFMA2 path) ----
__device__ __forceinline__ ull pk(float a, float b) {
    ull r;
    asm("mov.b64 %0, {%1,%2};" : "=l"(r) : "r"(__float_as_uint(a)), "r"(__float_as_uint(b)));
    return r;
}
__device__ __forceinline__ void upk(ull v, float& a, float& b) {
    unsigned x, y;
    asm("mov.b64 {%0,%1}, %2;" : "=r"(x), "=r"(y) : "l"(v));
    a = __uint_as_float(x); b = __uint_as_float(y);
}
__device__ __forceinline__ ull addx2(ull a, ull b) {
    ull r; asm("add.rn.f32x2 %0, %1, %2;" : "=l"(r) : "l"(a), "l"(b)); return r;
}
__device__ __forceinline__ ull mulx2(ull a, ull b) {
    ull r; asm("mul.rn.f32x2 %0, %1, %2;" : "=l"(r) : "l"(a), "l"(b)); return r;
}
__device__ __forceinline__ ull fmax2(ull a, ull b, ull c) {
    ull r; asm("fma.rn.f32x2 %0, %1, %2, %3;" : "=l"(r) : "l"(a), "l"(b), "l"(c)); return r;
}

// =====================================================================
// Kernel 1: XL = xWl + bl, XR = xWr + br, plus U = 0.6*att.XR, V = 0.6*att.XL
// Grid (32, 4), 512 threads. CTA handles 16 rows of one batch, both matrices.
// =====================================================================
__global__ void __launch_bounds__(512) gat_pre(
    const float* __restrict__ x,
    const float* __restrict__ Wl, const float* __restrict__ bl,
    const float* __restrict__ Wr, const float* __restrict__ br,
    const float* __restrict__ att)
{
    __shared__ __align__(16) float xs[16][128];
    const int b  = blockIdx.y;
    const int r0 = blockIdx.x * 16;
    const int t  = threadIdx.x;

    // cooperative load of 16 x-rows (2048 floats = 512 float4)
    ((float4*)xs)[t] = ((const float4*)(x + (size_t)(b * Nn + r0) * Dn))[t];
    __syncthreads();

    const int col = t & 127;
    const int q   = t >> 7;        // 0..3
    const int mat = q & 1;         // 0 -> Wl/XL/V, 1 -> Wr/XR/U
    const int rh  = q >> 1;        // row half (8 rows each)

    const float* W  = mat ? Wr : Wl;
    const float  bc = (mat ? br : bl)[col];

    float acc[8];
#pragma unroll
    for (int r = 0; r < 8; r++) acc[r] = 0.f;

    for (int k = 0; k < 128; k += 4) {
        const float w0 = W[(k + 0) * 128 + col];
        const float w1 = W[(k + 1) * 128 + col];
        const float w2 = W[(k + 2) * 128 + col];
        const float w3 = W[(k + 3) * 128 + col];
#pragma unroll
        for (int r = 0; r < 8; r++) {
            const float4 xv = *(const float4*)&xs[rh * 8 + r][k];
            acc[r] = fmaf(xv.x, w0, acc[r]);
            acc[r] = fmaf(xv.y, w1, acc[r]);
            acc[r] = fmaf(xv.z, w2, acc[r]);
            acc[r] = fmaf(xv.w, w3, acc[r]);
        }
    }

    float* Xo  = mat ? g_XR : g_XL;
    float* UVo = mat ? g_U  : g_V;
    const int   head = col >> 5;
    const float aw   = att[col];   // att[head*32 + c] == att[col]

#pragma unroll
    for (int r = 0; r < 8; r++) {
        const int row = r0 + rh * 8 + r;
        const float val = acc[r] + bc;
        Xo[(size_t)(b * Nn + row) * Dn + col] = val;
        float s = aw * val;
#pragma unroll
        for (int off = 16; off; off >>= 1)
            s += __shfl_xor_sync(0xffffffffu, s, off);
        if ((t & 31) == 0)
            UVo[(size_t)(b * Nn + row) * Hn + head] = 0.6f * s;
    }
}

// =====================================================================
// Kernel 2: fused score + masked online-softmax + weighted sum.
// Grid (32, 4), 256 threads. CTA = 16 target rows i, all heads.
// thread t: i_local = t&15, h = (t>>4)&3, rep = t>>6 (j stride 4).
// =====================================================================
__global__ void __launch_bounds__(256) gat_main(
    const int*   __restrict__ adj,
    const float* __restrict__ att,
    const float* __restrict__ bias,
    float*       __restrict__ out)
{
    const float L2E  = 1.4426950408889634f;
    const ull   ABS2 = 0x7FFFFFFF7FFFFFFFULL;

    const int b   = blockIdx.y;
    const int i0  = blockIdx.x * 16;
    const int t   = threadIdx.x;
    const int il  = t & 15;
    const int h   = (t >> 4) & 3;
    const int rep = t >> 6;
    const int i   = i0 + il;

    // persistent packed registers
    ull att2[16], xr2[16], acc2[16];
    {
        const float* ap  = att + h * 32;
        const float* xrp = g_XR + (size_t)(b * Nn + i) * Dn + h * 32;
#pragma unroll
        for (int k = 0; k < 16; k++) {
            att2[k] = pk(0.4f * ap[2 * k], 0.4f * ap[2 * k + 1]);
            xr2[k]  = pk(xrp[2 * k], xrp[2 * k + 1]);
            acc2[k] = 0ULL;
        }
    }
    const float u = g_U[(size_t)(b * Nn + i) * Hn + h];

    const float* xlb  = g_XL + (size_t)b * Nn * Dn;
    const float* vb   = g_V + (size_t)b * Nn * Hn;
    const int*   adjb = adj + (size_t)b * Nn * Nn;

    float m = -3.0e29f;   // sentinel init: masked e = -1e30 stays below it
    float l = 0.f;

    for (int j = rep; j < Nn; j += 4) {
        const int   av = adjb[j * Nn + i];            // edge j -> i
        const float v  = vb[j * Hn + h];

        const float4* xp = (const float4*)(xlb + j * Dn + h * 32);
        ull xl2[16];
#pragma unroll
        for (int k = 0; k < 8; k++) {
            const float4 q4 = xp[k];
            xl2[2 * k]     = pk(q4.x, q4.y);
            xl2[2 * k + 1] = pk(q4.z, q4.w);
        }

        // w = sum_c 0.4*att_c * |xr_c + xl_c|   (4-way packed accumulators)
        ull w0 = 0ULL, w1 = 0ULL, w2a = 0ULL, w3 = 0ULL;
#pragma unroll
        for (int k = 0; k < 16; k += 4) {
            const ull s0 = addx2(xr2[k],     xl2[k])     & ABS2;
            const ull s1 = addx2(xr2[k + 1], xl2[k + 1]) & ABS2;
            const ull s2 = addx2(xr2[k + 2], xl2[k + 2]) & ABS2;
            const ull s3 = addx2(xr2[k + 3], xl2[k + 3]) & ABS2;
            w0  = fmax2(att2[k],     s0, w0);
            w1  = fmax2(att2[k + 1], s1, w1);
            w2a = fmax2(att2[k + 2], s2, w2a);
            w3  = fmax2(att2[k + 3], s3, w3);
        }
        const ull ws = addx2(addx2(w0, w1), addx2(w2a, w3));
        float wa, wb; upk(ws, wa, wb);

        const bool valid = (av != 0) || (j == i);
        const float e = valid ? (u + v + wa + wb) : -1.0e30f;

        float p;
        if (e > m) {
            const float corr = exp2f((m - e) * L2E);
            const ull c2 = pk(corr, corr);
#pragma unroll
            for (int k = 0; k < 16; k++) acc2[k] = mulx2(acc2[k], c2);
            l *= corr;
            m  = e;
            p  = 1.f;
        } else {
            p = exp2f((e - m) * L2E);   // masked: exp2(-huge) = 0
        }
        l += p;
        const ull p2 = pk(p, p);
#pragma unroll
        for (int k = 0; k < 16; k++) acc2[k] = fmax2(p2, xl2[k], acc2[k]);
    }

    // ---- combine the 4 rep-partials per (i,h) ----
    __shared__ float sm_m[4][64], sm_l[4][64], sm_L[64];
    __shared__ float sm_acc[64][33];   // padded: conflict-free

    const int ih = t & 63;   // il + 16*h
    sm_m[rep][ih] = m;
    sm_l[rep][ih] = l;
    __syncthreads();

    const float M = fmaxf(fmaxf(sm_m[0][ih], sm_m[1][ih]),
                          fmaxf(sm_m[2][ih], sm_m[3][ih]));
    float L = 0.f;
#pragma unroll
    for (int r = 0; r < 4; r++)
        L += sm_l[r][ih] * exp2f((sm_m[r][ih] - M) * L2E);
    if (rep == 0) sm_L[ih] = L;

    const float sc = exp2f((m - M) * L2E);
    float av_[32];
#pragma unroll
    for (int k = 0; k < 16; k++) upk(acc2[k], av_[2 * k], av_[2 * k + 1]);

#pragma unroll
    for (int r = 0; r < 4; r++) {
        if (rep == r) {
            if (r == 0) {
#pragma unroll
                for (int c = 0; c < 32; c++) sm_acc[ih][c] = av_[c] * sc;
            } else {
#pragma unroll
                for (int c = 0; c < 32; c++) sm_acc[ih][c] += av_[c] * sc;
            }
        }
        __syncthreads();
    }

    // ---- normalize + bias, coalesced write ----
    float* ob = out + (size_t)(b * Nn + i0) * Dn;
    for (int idx = t; idx < 16 * Dn; idx += 256) {
        const int ir = idx >> 7;
        const int c  = idx & 127;
        const int k2 = ir + 16 * (c >> 5);
        ob[idx] = sm_acc[k2][c & 31] / sm_L[k2] + bias[c];
    }
}

extern "C" void kernel_launch(void* const* d_in, const int* in_sizes, int n_in,
                              void* d_out, int out_size) {
    const float* x    = (const float*)d_in[0];
    const int*   adj  = (const int*)  d_in[1];
    const float* Wl   = (const float*)d_in[2];
    const float* bl   = (const float*)d_in[3];
    const float* Wr   = (const float*)d_in[4];
    const float* br   = (const float*)d_in[5];
    const float* att  = (const float*)d_in[6];
    const float* bias = (const float*)d_in[7];
    float* out = (float*)d_out;

    gat_pre <<<dim3(Nn / 16, Bn), 512>>>(x, Wl, bl, Wr, br, att);
    gat_main<<<dim3(Nn / 16, Bn), 256>>>(adj, att, bias, out);
}